// round 2
// baseline (speedup 1.0000x reference)
#include <cuda_runtime.h>
#include <cstdint>

#define N_NODES 50000
#define N_EDGES 800000
#define D_MODEL 128
#define N_HEADS 8
#define D_HEAD  16

// ---------------- scratch (static device globals; no allocation) -------------
__device__ __align__(16) float d_q[N_NODES * D_MODEL];
__device__ __align__(16) float d_k[N_NODES * D_MODEL];
__device__ __align__(16) float d_v[N_NODES * D_MODEL];
__device__ __align__(16) float d_e[N_EDGES * N_HEADS];
__device__ __align__(16) float d_s[N_NODES * N_HEADS];
__device__ __align__(16) float d_agg[N_NODES * D_MODEL];
__device__ int d_src[N_EDGES];
__device__ int d_dst[N_EDGES];
__device__ int d_idx_is64;

// ---------------- kernel A: detect edge_index dtype ---------------------------
// If the buffer is int64 (values >= 0, < 2^31), every odd 32-bit word of the
// first 64 entries is 0. For int32 random indices in [0, 50000) the chance of
// 64 consecutive zeros is ~0, so this discriminates deterministically.
__global__ void detect_idx_kernel(const int* __restrict__ w) {
    int all_zero = 1;
    #pragma unroll
    for (int i = 0; i < 64; i++)
        if (w[2 * i + 1] != 0) all_zero = 0;
    d_idx_is64 = all_zero;
}

// ---------------- kernel B: convert indices to int32 src/dst -----------------
__global__ void conv_idx_kernel(const void* __restrict__ ei) {
    const int i = blockIdx.x * blockDim.x + threadIdx.x;
    if (i >= 2 * N_EDGES) return;
    int v;
    if (d_idx_is64) v = (int)((const long long*)ei)[i];
    else            v = ((const int*)ei)[i];
    if (i < N_EDGES) d_src[i] = v;
    else             d_dst[i - N_EDGES] = v;
}

// ---------------- kernel 0: zero the accumulators ----------------------------
__global__ void zero_kernel() {
    int i = blockIdx.x * blockDim.x + threadIdx.x;
    if (i < N_NODES * N_HEADS) d_s[i] = 0.0f;
    if (i < N_NODES * D_MODEL) d_agg[i] = 0.0f;
}

// ---------------- kernel 1: fused layernorm + QKV GEMM -----------------------
// 16 rows per CTA, 256 threads. Weights tiled through SMEM (64 cols/tile).
__global__ __launch_bounds__(256) void ln_qkv_kernel(
    const float* __restrict__ x,
    const float* __restrict__ qkv_w,   // [128, 384] row-major
    const float* __restrict__ qkv_b,   // [384]
    const float* __restrict__ ln_g,    // [128]
    const float* __restrict__ ln_b)    // [128]
{
    __shared__ float sh_h[16][D_MODEL];     // 8 KB
    __shared__ float sh_w[D_MODEL][64];     // 32 KB

    const int tid  = threadIdx.x;
    const int warp = tid >> 5;
    const int lane = tid & 31;
    const int row0 = blockIdx.x * 16;

    // ---- layernorm: warp w handles rows w and w+8 ----
    for (int rr = warp; rr < 16; rr += 8) {
        const int row = row0 + rr;
        float4 xv = reinterpret_cast<const float4*>(x)[row * 32 + lane];
        float sum = xv.x + xv.y + xv.z + xv.w;
        float sq  = xv.x * xv.x + xv.y * xv.y + xv.z * xv.z + xv.w * xv.w;
        #pragma unroll
        for (int o = 16; o > 0; o >>= 1) {
            sum += __shfl_xor_sync(0xffffffffu, sum, o);
            sq  += __shfl_xor_sync(0xffffffffu, sq, o);
        }
        const float mean = sum * (1.0f / 128.0f);
        const float var  = sq * (1.0f / 128.0f) - mean * mean;
        const float rstd = rsqrtf(var + 1e-5f);
        float4 gv = reinterpret_cast<const float4*>(ln_g)[lane];
        float4 bv = reinterpret_cast<const float4*>(ln_b)[lane];
        float4 h;
        h.x = (xv.x - mean) * rstd * gv.x + bv.x;
        h.y = (xv.y - mean) * rstd * gv.y + bv.y;
        h.z = (xv.z - mean) * rstd * gv.z + bv.z;
        h.w = (xv.w - mean) * rstd * gv.w + bv.w;
        reinterpret_cast<float4*>(sh_h[rr])[lane] = h;
    }
    __syncthreads();

    // ---- GEMM: out[16][384] in three 64-col tiles ----
    const int cc = tid & 63;          // column within tile
    const int rb = (tid >> 6) * 4;    // row base (4 rows per thread)

    for (int c0 = 0; c0 < 384; c0 += 64) {
        for (int i = tid; i < D_MODEL * 64; i += 256)
            sh_w[i >> 6][i & 63] = qkv_w[(i >> 6) * 384 + c0 + (i & 63)];
        __syncthreads();

        float a0 = 0.f, a1 = 0.f, a2 = 0.f, a3 = 0.f;
        #pragma unroll 8
        for (int k = 0; k < D_MODEL; k++) {
            const float wv = sh_w[k][cc];
            a0 += sh_h[rb + 0][k] * wv;
            a1 += sh_h[rb + 1][k] * wv;
            a2 += sh_h[rb + 2][k] * wv;
            a3 += sh_h[rb + 3][k] * wv;
        }
        const int   col  = c0 + cc;
        const float bias = qkv_b[col];
        float* dstp = (col < 128) ? d_q : (col < 256) ? d_k : d_v;
        const int cl = col & 127;
        dstp[(row0 + rb + 0) * D_MODEL + cl] = a0 + bias;
        dstp[(row0 + rb + 1) * D_MODEL + cl] = a1 + bias;
        dstp[(row0 + rb + 2) * D_MODEL + cl] = a2 + bias;
        dstp[(row0 + rb + 3) * D_MODEL + cl] = a3 + bias;
        __syncthreads();
    }
}

// ---------------- kernel 2: edge scores -> exp -> segment sum ----------------
// One warp per edge. Lane l handles dims [4l, 4l+4); head = l/4.
// No max-subtraction: attn = e/s is shift-invariant and scores are O(1)
// (layernormed inputs through 1/sqrt(D) weights), so exp cannot overflow.
__global__ __launch_bounds__(256) void edge_exp_kernel(
    const float* __restrict__ edge_attr)
{
    const int e = blockIdx.x * 8 + (threadIdx.x >> 5);
    if (e >= N_EDGES) return;
    const int lane = threadIdx.x & 31;
    const int src = d_src[e];
    const int dst = d_dst[e];

    float4 qv = reinterpret_cast<const float4*>(d_q)[dst * 32 + lane];
    float4 kv = reinterpret_cast<const float4*>(d_k)[src * 32 + lane];
    float4 av = reinterpret_cast<const float4*>(edge_attr)[e * 32 + lane];

    float p = qv.x * (kv.x + av.x) + qv.y * (kv.y + av.y)
            + qv.z * (kv.z + av.z) + qv.w * (kv.w + av.w);
    p += __shfl_xor_sync(0xffffffffu, p, 1);
    p += __shfl_xor_sync(0xffffffffu, p, 2);

    if ((lane & 3) == 0) {
        const int h = lane >> 2;
        const float ex = __expf(p * 0.25f);   // D_HEAD^-0.5 = 0.25
        d_e[e * N_HEADS + h] = ex;
        atomicAdd(&d_s[dst * N_HEADS + h], ex);
    }
}

// ---------------- kernel 3: aggregate messages (scatter-add) -----------------
// One warp per edge; vectorized f32x4 global reduction (quarter the atomic ops).
__global__ __launch_bounds__(256) void aggregate_kernel()
{
    const int e = blockIdx.x * 8 + (threadIdx.x >> 5);
    if (e >= N_EDGES) return;
    const int lane = threadIdx.x & 31;
    const int src = d_src[e];
    const int dst = d_dst[e];
    const int h = lane >> 2;

    const float attn = d_e[e * N_HEADS + h] / fmaxf(d_s[dst * N_HEADS + h], 1e-16f);
    float4 vv = reinterpret_cast<const float4*>(d_v)[src * 32 + lane];
    float* p = &d_agg[dst * D_MODEL + lane * 4];
    asm volatile("red.global.add.v4.f32 [%0], {%1, %2, %3, %4};"
                 :: "l"(p), "f"(vv.x * attn), "f"(vv.y * attn),
                    "f"(vv.z * attn), "f"(vv.w * attn)
                 : "memory");
}

// ---------------- kernel 4: output projection + bias + residual --------------
__global__ __launch_bounds__(256) void out_proj_kernel(
    const float* __restrict__ x,
    const float* __restrict__ out_w,   // [128, 128] row-major
    const float* __restrict__ out_b,   // [128]
    float* __restrict__ out)
{
    __shared__ float sh_a[16][D_MODEL];
    __shared__ float sh_w[D_MODEL][64];

    const int tid  = threadIdx.x;
    const int row0 = blockIdx.x * 16;

    for (int i = tid; i < 16 * 32; i += 256)
        reinterpret_cast<float4*>(sh_a)[i] =
            reinterpret_cast<const float4*>(d_agg)[row0 * 32 + i];
    __syncthreads();

    const int cc = tid & 63;
    const int rb = (tid >> 6) * 4;

    for (int c0 = 0; c0 < 128; c0 += 64) {
        for (int i = tid; i < D_MODEL * 64; i += 256)
            sh_w[i >> 6][i & 63] = out_w[(i >> 6) * 128 + c0 + (i & 63)];
        __syncthreads();

        float a0 = 0.f, a1 = 0.f, a2 = 0.f, a3 = 0.f;
        #pragma unroll 8
        for (int k = 0; k < D_MODEL; k++) {
            const float wv = sh_w[k][cc];
            a0 += sh_a[rb + 0][k] * wv;
            a1 += sh_a[rb + 1][k] * wv;
            a2 += sh_a[rb + 2][k] * wv;
            a3 += sh_a[rb + 3][k] * wv;
        }
        const int col = c0 + cc;
        const float bias = out_b[col];
        out[(row0 + rb + 0) * D_MODEL + col] = a0 + bias + x[(row0 + rb + 0) * D_MODEL + col];
        out[(row0 + rb + 1) * D_MODEL + col] = a1 + bias + x[(row0 + rb + 1) * D_MODEL + col];
        out[(row0 + rb + 2) * D_MODEL + col] = a2 + bias + x[(row0 + rb + 2) * D_MODEL + col];
        out[(row0 + rb + 3) * D_MODEL + col] = a3 + bias + x[(row0 + rb + 3) * D_MODEL + col];
        __syncthreads();
    }
}

// ---------------- launcher ----------------------------------------------------
extern "C" void kernel_launch(void* const* d_in, const int* in_sizes, int n_in,
                              void* d_out, int out_size)
{
    const float* x      = (const float*)d_in[0];
    const float* ea     = (const float*)d_in[1];
    const float* qkv_w  = (const float*)d_in[2];
    const float* qkv_b  = (const float*)d_in[3];
    const float* out_w  = (const float*)d_in[4];
    const float* out_b  = (const float*)d_in[5];
    const float* ln_g   = (const float*)d_in[6];
    const float* ln_b   = (const float*)d_in[7];
    const void*  ei     = d_in[8];
    float*       out    = (float*)d_out;

    detect_idx_kernel<<<1, 1>>>((const int*)ei);
    conv_idx_kernel<<<(2 * N_EDGES + 255) / 256, 256>>>(ei);
    zero_kernel<<<(N_NODES * D_MODEL + 255) / 256, 256>>>();
    ln_qkv_kernel<<<N_NODES / 16, 256>>>(x, qkv_w, qkv_b, ln_g, ln_b);
    edge_exp_kernel<<<N_EDGES / 8, 256>>>(ea);
    aggregate_kernel<<<N_EDGES / 8, 256>>>();
    out_proj_kernel<<<N_NODES / 16, 256>>>(x, out_w, out_b, out);
}

// round 3
// speedup vs baseline: 1.4910x; 1.4910x over previous
#include <cuda_runtime.h>
#include <cstdint>

#define N_NODES 50000
#define N_EDGES 800000
#define D_MODEL 128
#define N_HEADS 8
#define D_HEAD  16

// ---------------- scratch (static device globals; no allocation) -------------
__device__ __align__(16) float d_q[N_NODES * D_MODEL];
__device__ __align__(16) float d_k[N_NODES * D_MODEL];
__device__ __align__(16) float d_v[N_NODES * D_MODEL];
__device__ __align__(16) float d_s[N_NODES * N_HEADS];
__device__ __align__(16) float d_agg[N_NODES * D_MODEL];
__device__ int d_src[N_EDGES];
__device__ int d_dst[N_EDGES];
__device__ int d_idx_is64;

// ---------------- kernel A: detect edge_index dtype ---------------------------
__global__ void detect_idx_kernel(const int* __restrict__ w) {
    int all_zero = 1;
    #pragma unroll
    for (int i = 0; i < 64; i++)
        if (w[2 * i + 1] != 0) all_zero = 0;
    d_idx_is64 = all_zero;
}

// ---------------- kernel B: convert indices to int32 src/dst -----------------
__global__ void conv_idx_kernel(const void* __restrict__ ei) {
    const int i = blockIdx.x * blockDim.x + threadIdx.x;
    if (i >= 2 * N_EDGES) return;
    int v;
    if (d_idx_is64) v = (int)((const long long*)ei)[i];
    else            v = ((const int*)ei)[i];
    if (i < N_EDGES) d_src[i] = v;
    else             d_dst[i - N_EDGES] = v;
}

// ---------------- kernel 0: zero the accumulators ----------------------------
__global__ void zero_kernel() {
    int i = blockIdx.x * blockDim.x + threadIdx.x;
    if (i < N_NODES * N_HEADS) d_s[i] = 0.0f;
    if (i < N_NODES * D_MODEL) d_agg[i] = 0.0f;
}

// ---------------- kernel 1: fused layernorm + QKV GEMM -----------------------
// 32 rows/CTA, 256 threads. Per-thread tile: 4 rows x 4 cols (float4).
// Warp w owns rows 4w..4w+3; lane owns float4 col group `lane` of the
// 128-wide col tile. Inner loop: 1 LDS.128 (W) + 4 LDS.32 broadcast (h)
// per 16 FFMA -> FMA-pipe bound, not LDS bound.
__global__ __launch_bounds__(256) void ln_qkv_kernel(
    const float* __restrict__ x,
    const float* __restrict__ qkv_w,   // [128, 384] row-major
    const float* __restrict__ qkv_b,   // [384]
    const float* __restrict__ ln_g,    // [128]
    const float* __restrict__ ln_b)    // [128]
{
    __shared__ float  sh_h[32][D_MODEL];   // 16 KB
    __shared__ float4 sh_w4[32][32];       // 16 KB (k-chunk x 128 cols)

    const int tid  = threadIdx.x;
    const int warp = tid >> 5;
    const int lane = tid & 31;
    const int row0 = blockIdx.x * 32;

    // ---- layernorm: warp w handles rows 4w..4w+3 ----
    #pragma unroll
    for (int r = 0; r < 4; r++) {
        const int rr  = warp * 4 + r;
        const int row = min(row0 + rr, N_NODES - 1);
        float4 xv = reinterpret_cast<const float4*>(x)[row * 32 + lane];
        float sum = xv.x + xv.y + xv.z + xv.w;
        float sq  = xv.x * xv.x + xv.y * xv.y + xv.z * xv.z + xv.w * xv.w;
        #pragma unroll
        for (int o = 16; o > 0; o >>= 1) {
            sum += __shfl_xor_sync(0xffffffffu, sum, o);
            sq  += __shfl_xor_sync(0xffffffffu, sq, o);
        }
        const float mean = sum * (1.0f / 128.0f);
        const float var  = sq * (1.0f / 128.0f) - mean * mean;
        const float rstd = rsqrtf(var + 1e-5f);
        float4 gv = reinterpret_cast<const float4*>(ln_g)[lane];
        float4 bv = reinterpret_cast<const float4*>(ln_b)[lane];
        float4 h;
        h.x = (xv.x - mean) * rstd * gv.x + bv.x;
        h.y = (xv.y - mean) * rstd * gv.y + bv.y;
        h.z = (xv.z - mean) * rstd * gv.z + bv.z;
        h.w = (xv.w - mean) * rstd * gv.w + bv.w;
        reinterpret_cast<float4*>(&sh_h[rr][0])[lane] = h;
    }

    // ---- GEMM: 3 col tiles of 128 (q / k / v) ----
    for (int c0 = 0; c0 < 384; c0 += 128) {
        float4 acc0 = {0,0,0,0}, acc1 = {0,0,0,0}, acc2 = {0,0,0,0}, acc3 = {0,0,0,0};

        for (int k0 = 0; k0 < 128; k0 += 32) {
            __syncthreads();
            #pragma unroll
            for (int kk = warp; kk < 32; kk += 8)
                sh_w4[kk][lane] =
                    reinterpret_cast<const float4*>(qkv_w + (k0 + kk) * 384 + c0)[lane];
            __syncthreads();

            #pragma unroll
            for (int k = 0; k < 32; k++) {
                const float4 wv = sh_w4[k][lane];
                const float h0 = sh_h[warp * 4 + 0][k0 + k];
                const float h1 = sh_h[warp * 4 + 1][k0 + k];
                const float h2 = sh_h[warp * 4 + 2][k0 + k];
                const float h3 = sh_h[warp * 4 + 3][k0 + k];
                acc0.x += h0 * wv.x; acc0.y += h0 * wv.y; acc0.z += h0 * wv.z; acc0.w += h0 * wv.w;
                acc1.x += h1 * wv.x; acc1.y += h1 * wv.y; acc1.z += h1 * wv.z; acc1.w += h1 * wv.w;
                acc2.x += h2 * wv.x; acc2.y += h2 * wv.y; acc2.z += h2 * wv.z; acc2.w += h2 * wv.w;
                acc3.x += h3 * wv.x; acc3.y += h3 * wv.y; acc3.z += h3 * wv.z; acc3.w += h3 * wv.w;
            }
        }

        const float4 bias = reinterpret_cast<const float4*>(qkv_b + c0)[lane];
        float* dstp = (c0 == 0) ? d_q : (c0 == 128) ? d_k : d_v;
        acc0.x += bias.x; acc0.y += bias.y; acc0.z += bias.z; acc0.w += bias.w;
        acc1.x += bias.x; acc1.y += bias.y; acc1.z += bias.z; acc1.w += bias.w;
        acc2.x += bias.x; acc2.y += bias.y; acc2.z += bias.z; acc2.w += bias.w;
        acc3.x += bias.x; acc3.y += bias.y; acc3.z += bias.z; acc3.w += bias.w;
        const int rbase = row0 + warp * 4;
        if (rbase + 0 < N_NODES) reinterpret_cast<float4*>(dstp + (rbase + 0) * 128)[lane] = acc0;
        if (rbase + 1 < N_NODES) reinterpret_cast<float4*>(dstp + (rbase + 1) * 128)[lane] = acc1;
        if (rbase + 2 < N_NODES) reinterpret_cast<float4*>(dstp + (rbase + 2) * 128)[lane] = acc2;
        if (rbase + 3 < N_NODES) reinterpret_cast<float4*>(dstp + (rbase + 3) * 128)[lane] = acc3;
    }
}

// ---------------- kernel 2: fused edge pass -----------------------------------
// One warp per edge. Softmax normalization is linear, so we accumulate the
// UNNORMALIZED message sum (e*v) and the partition function s in one sweep;
// division by s happens in out_proj. No max-subtraction: scores are O(few)
// (layernormed inputs through 1/sqrt(D) weights), exp cannot overflow.
__global__ __launch_bounds__(256) void edge_fused_kernel(
    const float* __restrict__ edge_attr)
{
    const int e = blockIdx.x * 8 + (threadIdx.x >> 5);
    if (e >= N_EDGES) return;
    const int lane = threadIdx.x & 31;
    const int src = d_src[e];
    const int dst = d_dst[e];

    float4 qv = reinterpret_cast<const float4*>(d_q)[dst * 32 + lane];
    float4 kv = reinterpret_cast<const float4*>(d_k)[src * 32 + lane];
    float4 av = reinterpret_cast<const float4*>(edge_attr)[e * 32 + lane];

    float p = qv.x * (kv.x + av.x) + qv.y * (kv.y + av.y)
            + qv.z * (kv.z + av.z) + qv.w * (kv.w + av.w);
    p += __shfl_xor_sync(0xffffffffu, p, 1);
    p += __shfl_xor_sync(0xffffffffu, p, 2);   // all 4 lanes of a head share p

    const float ex = __expf(p * 0.25f);        // D_HEAD^-0.5 = 0.25
    if ((lane & 3) == 0)
        atomicAdd(&d_s[dst * N_HEADS + (lane >> 2)], ex);

    float4 vv = reinterpret_cast<const float4*>(d_v)[src * 32 + lane];
    float* pdst = &d_agg[dst * D_MODEL + lane * 4];
    asm volatile("red.global.add.v4.f32 [%0], {%1, %2, %3, %4};"
                 :: "l"(pdst), "f"(vv.x * ex), "f"(vv.y * ex),
                    "f"(vv.z * ex), "f"(vv.w * ex)
                 : "memory");
}

// ---------------- kernel 3: normalize + output projection + residual ---------
// Same 4x4 register blocking as ln_qkv. agg is divided by s per head on load.
__global__ __launch_bounds__(256) void out_proj_kernel(
    const float* __restrict__ x,
    const float* __restrict__ out_w,   // [128, 128] row-major
    const float* __restrict__ out_b,   // [128]
    float* __restrict__ out)
{
    __shared__ float  sh_a[32][D_MODEL];   // 16 KB
    __shared__ float4 sh_w4[32][32];       // 16 KB

    const int tid  = threadIdx.x;
    const int warp = tid >> 5;
    const int lane = tid & 31;
    const int row0 = blockIdx.x * 32;

    // load agg, normalized by segment sum (per head: float4 group g -> head g>>2)
    for (int i = tid; i < 32 * 32; i += 256) {
        const int r   = i >> 5;
        const int g   = i & 31;
        const int row = min(row0 + r, N_NODES - 1);
        float4 a = reinterpret_cast<const float4*>(d_agg)[row * 32 + g];
        const float inv = 1.0f / fmaxf(d_s[row * N_HEADS + (g >> 2)], 1e-16f);
        a.x *= inv; a.y *= inv; a.z *= inv; a.w *= inv;
        reinterpret_cast<float4*>(&sh_a[r][0])[g] = a;
    }

    float4 acc0 = {0,0,0,0}, acc1 = {0,0,0,0}, acc2 = {0,0,0,0}, acc3 = {0,0,0,0};

    for (int k0 = 0; k0 < 128; k0 += 32) {
        __syncthreads();
        #pragma unroll
        for (int kk = warp; kk < 32; kk += 8)
            sh_w4[kk][lane] =
                reinterpret_cast<const float4*>(out_w + (k0 + kk) * 128)[lane];
        __syncthreads();

        #pragma unroll
        for (int k = 0; k < 32; k++) {
            const float4 wv = sh_w4[k][lane];
            const float a0 = sh_a[warp * 4 + 0][k0 + k];
            const float a1 = sh_a[warp * 4 + 1][k0 + k];
            const float a2 = sh_a[warp * 4 + 2][k0 + k];
            const float a3 = sh_a[warp * 4 + 3][k0 + k];
            acc0.x += a0 * wv.x; acc0.y += a0 * wv.y; acc0.z += a0 * wv.z; acc0.w += a0 * wv.w;
            acc1.x += a1 * wv.x; acc1.y += a1 * wv.y; acc1.z += a1 * wv.z; acc1.w += a1 * wv.w;
            acc2.x += a2 * wv.x; acc2.y += a2 * wv.y; acc2.z += a2 * wv.z; acc2.w += a2 * wv.w;
            acc3.x += a3 * wv.x; acc3.y += a3 * wv.y; acc3.z += a3 * wv.z; acc3.w += a3 * wv.w;
        }
    }

    const float4 bias = reinterpret_cast<const float4*>(out_b)[lane];
    const int rbase = row0 + warp * 4;
    #pragma unroll
    for (int r = 0; r < 4; r++) {
        const int row = rbase + r;
        if (row >= N_NODES) break;
        float4 acc = (r == 0) ? acc0 : (r == 1) ? acc1 : (r == 2) ? acc2 : acc3;
        float4 xv = reinterpret_cast<const float4*>(x)[row * 32 + lane];
        float4 o;
        o.x = acc.x + bias.x + xv.x;
        o.y = acc.y + bias.y + xv.y;
        o.z = acc.z + bias.z + xv.z;
        o.w = acc.w + bias.w + xv.w;
        reinterpret_cast<float4*>(out + row * 128)[lane] = o;
    }
}

// ---------------- launcher ----------------------------------------------------
extern "C" void kernel_launch(void* const* d_in, const int* in_sizes, int n_in,
                              void* d_out, int out_size)
{
    const float* x      = (const float*)d_in[0];
    const float* ea     = (const float*)d_in[1];
    const float* qkv_w  = (const float*)d_in[2];
    const float* qkv_b  = (const float*)d_in[3];
    const float* out_w  = (const float*)d_in[4];
    const float* out_b  = (const float*)d_in[5];
    const float* ln_g   = (const float*)d_in[6];
    const float* ln_b   = (const float*)d_in[7];
    const void*  ei     = d_in[8];
    float*       out    = (float*)d_out;

    const int node_tiles = (N_NODES + 31) / 32;   // 1563

    detect_idx_kernel<<<1, 1>>>((const int*)ei);
    conv_idx_kernel<<<(2 * N_EDGES + 255) / 256, 256>>>(ei);
    zero_kernel<<<(N_NODES * D_MODEL + 255) / 256, 256>>>();
    ln_qkv_kernel<<<node_tiles, 256>>>(x, qkv_w, qkv_b, ln_g, ln_b);
    edge_fused_kernel<<<N_EDGES / 8, 256>>>(ea);
    out_proj_kernel<<<node_tiles, 256>>>(x, out_w, out_b, out);
}

// round 4
// speedup vs baseline: 1.6279x; 1.0918x over previous
#include <cuda_runtime.h>
#include <cstdint>

#define N_NODES 50000
#define N_EDGES 800000
#define D_MODEL 128
#define N_HEADS 8
#define D_HEAD  16

// ---------------- scratch (static device globals; no allocation) -------------
__device__ __align__(16) float d_q[N_NODES * D_MODEL];
__device__ __align__(16) float d_k[N_NODES * D_MODEL];
__device__ __align__(16) float d_v[N_NODES * D_MODEL];
__device__ __align__(16) float d_agg[N_NODES * D_MODEL];
__device__ int  d_src[N_EDGES];
__device__ int  d_dst[N_EDGES];
__device__ int  d_cnt[N_NODES];
__device__ int  d_rowptr[N_NODES + 1];
__device__ int  d_woff[N_NODES];
__device__ int2 d_csr[N_EDGES];          // {src, edge_id} sorted by dst
__device__ int  d_idx_is64;

// ---------------- kernel A: detect edge_index dtype ---------------------------
__global__ void detect_idx_kernel(const int* __restrict__ w) {
    int all_zero = 1;
    #pragma unroll
    for (int i = 0; i < 64; i++)
        if (w[2 * i + 1] != 0) all_zero = 0;
    d_idx_is64 = all_zero;
}

// ---------------- kernel B: zero degree counts (graph replays need re-init) --
__global__ void zero_cnt_kernel() {
    const int i = blockIdx.x * blockDim.x + threadIdx.x;
    if (i < N_NODES) d_cnt[i] = 0;
}

// ---------------- kernel C: convert indices to int32 + count degrees ---------
__global__ void conv_idx_kernel(const void* __restrict__ ei) {
    const int i = blockIdx.x * blockDim.x + threadIdx.x;
    if (i >= 2 * N_EDGES) return;
    int v;
    if (d_idx_is64) v = (int)((const long long*)ei)[i];
    else            v = ((const int*)ei)[i];
    if (i < N_EDGES) d_src[i] = v;
    else {
        d_dst[i - N_EDGES] = v;
        atomicAdd(&d_cnt[v], 1);
    }
}

// ---------------- kernel D: exclusive scan of degrees (single CTA) -----------
__global__ __launch_bounds__(1024) void scan_kernel() {
    __shared__ int wsum[32];
    __shared__ int carry;
    const int lane = threadIdx.x & 31;
    const int wid  = threadIdx.x >> 5;
    if (threadIdx.x == 0) carry = 0;
    __syncthreads();

    for (int base = 0; base < N_NODES; base += 1024) {
        const int i = base + (int)threadIdx.x;
        const int v = (i < N_NODES) ? d_cnt[i] : 0;
        // warp inclusive scan
        int x = v;
        #pragma unroll
        for (int o = 1; o < 32; o <<= 1) {
            int y = __shfl_up_sync(0xffffffffu, x, o);
            if (lane >= o) x += y;
        }
        if (lane == 31) wsum[wid] = x;
        __syncthreads();
        if (wid == 0) {
            int w = wsum[lane];
            #pragma unroll
            for (int o = 1; o < 32; o <<= 1) {
                int y = __shfl_up_sync(0xffffffffu, w, o);
                if (lane >= o) w += y;
            }
            wsum[lane] = w;
        }
        __syncthreads();
        const int incl = x + (wid > 0 ? wsum[wid - 1] : 0) + carry;
        if (i < N_NODES) {
            d_rowptr[i] = incl - v;
            d_woff[i]   = incl - v;
        }
        __syncthreads();                       // all reads of carry/wsum done
        if (threadIdx.x == 1023) carry = incl;
        __syncthreads();
    }
    if (threadIdx.x == 0) d_rowptr[N_NODES] = carry;
}

// ---------------- kernel E: scatter edges into CSR ----------------------------
__global__ void scatter_kernel() {
    const int e = blockIdx.x * blockDim.x + threadIdx.x;
    if (e >= N_EDGES) return;
    const int dst = d_dst[e];
    const int pos = atomicAdd(&d_woff[dst], 1);
    d_csr[pos] = make_int2(d_src[e], e);
}

// ---------------- kernel 1: fused layernorm + QKV GEMM -----------------------
// 32 rows/CTA, 256 threads, 4 rows x 4 cols per thread. Inner loop uses
// float4 broadcast loads for h (8 LDS per 64 FFMA).
__global__ __launch_bounds__(256) void ln_qkv_kernel(
    const float* __restrict__ x,
    const float* __restrict__ qkv_w,   // [128, 384] row-major
    const float* __restrict__ qkv_b,   // [384]
    const float* __restrict__ ln_g,    // [128]
    const float* __restrict__ ln_b)    // [128]
{
    __shared__ float4 sh_h4[32][32];   // 16 KB  (rows x 128 dims as float4)
    __shared__ float4 sh_w4[32][32];   // 16 KB  (k-chunk x 128 cols as float4)

    const int tid  = threadIdx.x;
    const int warp = tid >> 5;
    const int lane = tid & 31;
    const int row0 = blockIdx.x * 32;

    // ---- layernorm: warp w handles rows 4w..4w+3 ----
    #pragma unroll
    for (int r = 0; r < 4; r++) {
        const int rr  = warp * 4 + r;
        const int row = min(row0 + rr, N_NODES - 1);
        float4 xv = reinterpret_cast<const float4*>(x)[row * 32 + lane];
        float sum = xv.x + xv.y + xv.z + xv.w;
        float sq  = xv.x * xv.x + xv.y * xv.y + xv.z * xv.z + xv.w * xv.w;
        #pragma unroll
        for (int o = 16; o > 0; o >>= 1) {
            sum += __shfl_xor_sync(0xffffffffu, sum, o);
            sq  += __shfl_xor_sync(0xffffffffu, sq, o);
        }
        const float mean = sum * (1.0f / 128.0f);
        const float var  = sq * (1.0f / 128.0f) - mean * mean;
        const float rstd = rsqrtf(var + 1e-5f);
        float4 gv = reinterpret_cast<const float4*>(ln_g)[lane];
        float4 bv = reinterpret_cast<const float4*>(ln_b)[lane];
        float4 h;
        h.x = (xv.x - mean) * rstd * gv.x + bv.x;
        h.y = (xv.y - mean) * rstd * gv.y + bv.y;
        h.z = (xv.z - mean) * rstd * gv.z + bv.z;
        h.w = (xv.w - mean) * rstd * gv.w + bv.w;
        sh_h4[rr][lane] = h;
    }

    // ---- GEMM: 3 col tiles of 128 (q / k / v) ----
    for (int c0 = 0; c0 < 384; c0 += 128) {
        float4 acc0 = {0,0,0,0}, acc1 = {0,0,0,0}, acc2 = {0,0,0,0}, acc3 = {0,0,0,0};

        for (int k0 = 0; k0 < 128; k0 += 32) {
            __syncthreads();
            #pragma unroll
            for (int kk = warp; kk < 32; kk += 8)
                sh_w4[kk][lane] =
                    reinterpret_cast<const float4*>(qkv_w + (k0 + kk) * 384 + c0)[lane];
            __syncthreads();

            #pragma unroll
            for (int k4 = 0; k4 < 8; k4++) {
                const float4 h0 = sh_h4[warp * 4 + 0][(k0 >> 2) + k4];
                const float4 h1 = sh_h4[warp * 4 + 1][(k0 >> 2) + k4];
                const float4 h2 = sh_h4[warp * 4 + 2][(k0 >> 2) + k4];
                const float4 h3 = sh_h4[warp * 4 + 3][(k0 >> 2) + k4];
                const float ha0[4] = {h0.x, h0.y, h0.z, h0.w};
                const float ha1[4] = {h1.x, h1.y, h1.z, h1.w};
                const float ha2[4] = {h2.x, h2.y, h2.z, h2.w};
                const float ha3[4] = {h3.x, h3.y, h3.z, h3.w};
                #pragma unroll
                for (int j = 0; j < 4; j++) {
                    const float4 wv = sh_w4[k4 * 4 + j][lane];
                    acc0.x += ha0[j] * wv.x; acc0.y += ha0[j] * wv.y; acc0.z += ha0[j] * wv.z; acc0.w += ha0[j] * wv.w;
                    acc1.x += ha1[j] * wv.x; acc1.y += ha1[j] * wv.y; acc1.z += ha1[j] * wv.z; acc1.w += ha1[j] * wv.w;
                    acc2.x += ha2[j] * wv.x; acc2.y += ha2[j] * wv.y; acc2.z += ha2[j] * wv.z; acc2.w += ha2[j] * wv.w;
                    acc3.x += ha3[j] * wv.x; acc3.y += ha3[j] * wv.y; acc3.z += ha3[j] * wv.z; acc3.w += ha3[j] * wv.w;
                }
            }
        }

        const float4 bias = reinterpret_cast<const float4*>(qkv_b + c0)[lane];
        float* dstp = (c0 == 0) ? d_q : (c0 == 128) ? d_k : d_v;
        acc0.x += bias.x; acc0.y += bias.y; acc0.z += bias.z; acc0.w += bias.w;
        acc1.x += bias.x; acc1.y += bias.y; acc1.z += bias.z; acc1.w += bias.w;
        acc2.x += bias.x; acc2.y += bias.y; acc2.z += bias.z; acc2.w += bias.w;
        acc3.x += bias.x; acc3.y += bias.y; acc3.z += bias.z; acc3.w += bias.w;
        const int rbase = row0 + warp * 4;
        if (rbase + 0 < N_NODES) reinterpret_cast<float4*>(dstp + (rbase + 0) * 128)[lane] = acc0;
        if (rbase + 1 < N_NODES) reinterpret_cast<float4*>(dstp + (rbase + 1) * 128)[lane] = acc1;
        if (rbase + 2 < N_NODES) reinterpret_cast<float4*>(dstp + (rbase + 2) * 128)[lane] = acc2;
        if (rbase + 3 < N_NODES) reinterpret_cast<float4*>(dstp + (rbase + 3) * 128)[lane] = acc3;
    }
}

// ---------------- kernel 2: per-node attention aggregate (CSR) ---------------
// One warp per destination node. q loaded once; s and e*v accumulated in
// registers; normalization fused. No atomics, no zero-init.
// No max-subtraction: scores are O(few) (layernormed inputs through 1/sqrt(D)
// weights), exp cannot overflow; attn=e/s is shift-invariant.
__global__ __launch_bounds__(256) void node_attn_kernel(
    const float* __restrict__ edge_attr)
{
    const int n = blockIdx.x * 8 + (threadIdx.x >> 5);
    if (n >= N_NODES) return;
    const int lane = threadIdx.x & 31;
    const int beg = d_rowptr[n];
    const int end = d_rowptr[n + 1];

    const float4 qv = reinterpret_cast<const float4*>(d_q)[n * 32 + lane];
    float4 acc = {0.f, 0.f, 0.f, 0.f};
    float  s   = 0.f;

    for (int i = beg; i < end; i++) {
        const int2 ce  = d_csr[i];
        const int  src = ce.x;
        const int  eid = ce.y;

        float4 kv = reinterpret_cast<const float4*>(d_k)[src * 32 + lane];
        float4 av = reinterpret_cast<const float4*>(edge_attr)[eid * 32 + lane];

        float p = qv.x * (kv.x + av.x) + qv.y * (kv.y + av.y)
                + qv.z * (kv.z + av.z) + qv.w * (kv.w + av.w);
        p += __shfl_xor_sync(0xffffffffu, p, 1);
        p += __shfl_xor_sync(0xffffffffu, p, 2);   // 4 lanes/head share p

        const float ex = __expf(p * 0.25f);        // D_HEAD^-0.5
        s += ex;

        float4 vv = reinterpret_cast<const float4*>(d_v)[src * 32 + lane];
        acc.x += ex * vv.x; acc.y += ex * vv.y;
        acc.z += ex * vv.z; acc.w += ex * vv.w;
    }

    const float inv = 1.0f / fmaxf(s, 1e-16f);
    acc.x *= inv; acc.y *= inv; acc.z *= inv; acc.w *= inv;
    reinterpret_cast<float4*>(d_agg)[n * 32 + lane] = acc;
}

// ---------------- kernel 3: output projection + bias + residual --------------
__global__ __launch_bounds__(256) void out_proj_kernel(
    const float* __restrict__ x,
    const float* __restrict__ out_w,   // [128, 128] row-major
    const float* __restrict__ out_b,   // [128]
    float* __restrict__ out)
{
    __shared__ float4 sh_a4[32][32];   // 16 KB
    __shared__ float4 sh_w4[32][32];   // 16 KB

    const int tid  = threadIdx.x;
    const int warp = tid >> 5;
    const int lane = tid & 31;
    const int row0 = blockIdx.x * 32;

    for (int i = tid; i < 32 * 32; i += 256) {
        const int r   = i >> 5;
        const int g   = i & 31;
        const int row = min(row0 + r, N_NODES - 1);
        sh_a4[r][g] = reinterpret_cast<const float4*>(d_agg)[row * 32 + g];
    }

    float4 acc0 = {0,0,0,0}, acc1 = {0,0,0,0}, acc2 = {0,0,0,0}, acc3 = {0,0,0,0};

    for (int k0 = 0; k0 < 128; k0 += 32) {
        __syncthreads();
        #pragma unroll
        for (int kk = warp; kk < 32; kk += 8)
            sh_w4[kk][lane] =
                reinterpret_cast<const float4*>(out_w + (k0 + kk) * 128)[lane];
        __syncthreads();

        #pragma unroll
        for (int k4 = 0; k4 < 8; k4++) {
            const float4 a0 = sh_a4[warp * 4 + 0][(k0 >> 2) + k4];
            const float4 a1 = sh_a4[warp * 4 + 1][(k0 >> 2) + k4];
            const float4 a2 = sh_a4[warp * 4 + 2][(k0 >> 2) + k4];
            const float4 a3 = sh_a4[warp * 4 + 3][(k0 >> 2) + k4];
            const float aa0[4] = {a0.x, a0.y, a0.z, a0.w};
            const float aa1[4] = {a1.x, a1.y, a1.z, a1.w};
            const float aa2[4] = {a2.x, a2.y, a2.z, a2.w};
            const float aa3[4] = {a3.x, a3.y, a3.z, a3.w};
            #pragma unroll
            for (int j = 0; j < 4; j++) {
                const float4 wv = sh_w4[k4 * 4 + j][lane];
                acc0.x += aa0[j] * wv.x; acc0.y += aa0[j] * wv.y; acc0.z += aa0[j] * wv.z; acc0.w += aa0[j] * wv.w;
                acc1.x += aa1[j] * wv.x; acc1.y += aa1[j] * wv.y; acc1.z += aa1[j] * wv.z; acc1.w += aa1[j] * wv.w;
                acc2.x += aa2[j] * wv.x; acc2.y += aa2[j] * wv.y; acc2.z += aa2[j] * wv.z; acc2.w += aa2[j] * wv.w;
                acc3.x += aa3[j] * wv.x; acc3.y += aa3[j] * wv.y; acc3.z += aa3[j] * wv.z; acc3.w += aa3[j] * wv.w;
            }
        }
    }

    const float4 bias = reinterpret_cast<const float4*>(out_b)[lane];
    const int rbase = row0 + warp * 4;
    #pragma unroll
    for (int r = 0; r < 4; r++) {
        const int row = rbase + r;
        if (row >= N_NODES) break;
        float4 acc = (r == 0) ? acc0 : (r == 1) ? acc1 : (r == 2) ? acc2 : acc3;
        float4 xv = reinterpret_cast<const float4*>(x)[row * 32 + lane];
        float4 o;
        o.x = acc.x + bias.x + xv.x;
        o.y = acc.y + bias.y + xv.y;
        o.z = acc.z + bias.z + xv.z;
        o.w = acc.w + bias.w + xv.w;
        reinterpret_cast<float4*>(out + row * 128)[lane] = o;
    }
}

// ---------------- launcher ----------------------------------------------------
extern "C" void kernel_launch(void* const* d_in, const int* in_sizes, int n_in,
                              void* d_out, int out_size)
{
    const float* x      = (const float*)d_in[0];
    const float* ea     = (const float*)d_in[1];
    const float* qkv_w  = (const float*)d_in[2];
    const float* qkv_b  = (const float*)d_in[3];
    const float* out_w  = (const float*)d_in[4];
    const float* out_b  = (const float*)d_in[5];
    const float* ln_g   = (const float*)d_in[6];
    const float* ln_b   = (const float*)d_in[7];
    const void*  ei     = d_in[8];
    float*       out    = (float*)d_out;

    const int node_tiles = (N_NODES + 31) / 32;   // 1563

    detect_idx_kernel<<<1, 1>>>((const int*)ei);
    zero_cnt_kernel<<<(N_NODES + 255) / 256, 256>>>();
    conv_idx_kernel<<<(2 * N_EDGES + 255) / 256, 256>>>(ei);
    scan_kernel<<<1, 1024>>>();
    scatter_kernel<<<(N_EDGES + 255) / 256, 256>>>();
    ln_qkv_kernel<<<node_tiles, 256>>>(x, qkv_w, qkv_b, ln_g, ln_b);
    node_attn_kernel<<<(N_NODES + 7) / 8, 256>>>(ea);
    out_proj_kernel<<<node_tiles, 256>>>(x, out_w, out_b, out);
}

// round 5
// speedup vs baseline: 1.7579x; 1.0799x over previous
#include <cuda_runtime.h>
#include <cstdint>

#define N_NODES 50000
#define N_EDGES 800000
#define D_MODEL 128
#define N_HEADS 8
#define D_HEAD  16

// ---------------- scratch (static device globals; no allocation) -------------
__device__ __align__(16) float d_q[N_NODES * D_MODEL];
__device__ __align__(16) float d_k[N_NODES * D_MODEL];
__device__ __align__(16) float d_v[N_NODES * D_MODEL];
__device__ __align__(16) float d_agg[N_NODES * D_MODEL];
__device__ int  d_src[N_EDGES];
__device__ int  d_dst[N_EDGES];
__device__ int  d_cnt[N_NODES];
__device__ int  d_rowptr[N_NODES];       // start of each node's CSR segment
__device__ int  d_woff[N_NODES];         // scatter write cursor
__device__ int2 d_csr[N_EDGES];          // {src, edge_id} grouped by dst
__device__ int  d_gctr;                  // global range allocator
__device__ int  d_idx_is64;

// ---------------- kernel A: detect edge_index dtype ---------------------------
__global__ void detect_idx_kernel(const int* __restrict__ w) {
    int all_zero = 1;
    #pragma unroll
    for (int i = 0; i < 64; i++)
        if (w[2 * i + 1] != 0) all_zero = 0;
    d_idx_is64 = all_zero;
    d_gctr = 0;
}

// ---------------- kernel B: zero degree counts (graph replays re-init) -------
__global__ void zero_cnt_kernel() {
    const int i = blockIdx.x * blockDim.x + threadIdx.x;
    if (i < N_NODES) d_cnt[i] = 0;
}

// ---------------- kernel C: convert indices to int32 + count degrees ---------
__global__ void conv_idx_kernel(const void* __restrict__ ei) {
    const int i = blockIdx.x * blockDim.x + threadIdx.x;
    if (i >= 2 * N_EDGES) return;
    int v;
    if (d_idx_is64) v = (int)((const long long*)ei)[i];
    else            v = ((const int*)ei)[i];
    if (i < N_EDGES) d_src[i] = v;
    else {
        d_dst[i - N_EDGES] = v;
        atomicAdd(&d_cnt[v], 1);
    }
}

// ---------------- kernel D: allocate contiguous CSR ranges (no scan!) --------
// Segment order across nodes is arbitrary; only per-node contiguity matters.
__global__ void alloc_kernel() {
    const int n = blockIdx.x * blockDim.x + threadIdx.x;
    if (n >= N_NODES) return;
    const int c   = d_cnt[n];
    const int off = atomicAdd(&d_gctr, c);
    d_rowptr[n] = off;
    d_woff[n]   = off;
}

// ---------------- kernel E: scatter edges into CSR ----------------------------
__global__ void scatter_kernel() {
    const int e = blockIdx.x * blockDim.x + threadIdx.x;
    if (e >= N_EDGES) return;
    const int dst = d_dst[e];
    const int pos = atomicAdd(&d_woff[dst], 1);
    d_csr[pos] = make_int2(d_src[e], e);
}

// ---------------- kernel 1: fused layernorm + QKV GEMM -----------------------
// 32 rows/CTA, 256 threads, 4 rows x 4 cols per thread.
__global__ __launch_bounds__(256) void ln_qkv_kernel(
    const float* __restrict__ x,
    const float* __restrict__ qkv_w,   // [128, 384] row-major
    const float* __restrict__ qkv_b,   // [384]
    const float* __restrict__ ln_g,    // [128]
    const float* __restrict__ ln_b)    // [128]
{
    __shared__ float4 sh_h4[32][32];   // 16 KB  (rows x 128 dims as float4)
    __shared__ float4 sh_w4[32][32];   // 16 KB  (k-chunk x 128 cols as float4)

    const int tid  = threadIdx.x;
    const int warp = tid >> 5;
    const int lane = tid & 31;
    const int row0 = blockIdx.x * 32;

    // ---- layernorm: warp w handles rows 4w..4w+3 ----
    #pragma unroll
    for (int r = 0; r < 4; r++) {
        const int rr  = warp * 4 + r;
        const int row = min(row0 + rr, N_NODES - 1);
        float4 xv = reinterpret_cast<const float4*>(x)[row * 32 + lane];
        float sum = xv.x + xv.y + xv.z + xv.w;
        float sq  = xv.x * xv.x + xv.y * xv.y + xv.z * xv.z + xv.w * xv.w;
        #pragma unroll
        for (int o = 16; o > 0; o >>= 1) {
            sum += __shfl_xor_sync(0xffffffffu, sum, o);
            sq  += __shfl_xor_sync(0xffffffffu, sq, o);
        }
        const float mean = sum * (1.0f / 128.0f);
        const float var  = sq * (1.0f / 128.0f) - mean * mean;
        const float rstd = rsqrtf(var + 1e-5f);
        float4 gv = reinterpret_cast<const float4*>(ln_g)[lane];
        float4 bv = reinterpret_cast<const float4*>(ln_b)[lane];
        float4 h;
        h.x = (xv.x - mean) * rstd * gv.x + bv.x;
        h.y = (xv.y - mean) * rstd * gv.y + bv.y;
        h.z = (xv.z - mean) * rstd * gv.z + bv.z;
        h.w = (xv.w - mean) * rstd * gv.w + bv.w;
        sh_h4[rr][lane] = h;
    }

    // ---- GEMM: 3 col tiles of 128 (q / k / v) ----
    for (int c0 = 0; c0 < 384; c0 += 128) {
        float4 acc0 = {0,0,0,0}, acc1 = {0,0,0,0}, acc2 = {0,0,0,0}, acc3 = {0,0,0,0};

        for (int k0 = 0; k0 < 128; k0 += 32) {
            __syncthreads();
            #pragma unroll
            for (int kk = warp; kk < 32; kk += 8)
                sh_w4[kk][lane] =
                    reinterpret_cast<const float4*>(qkv_w + (k0 + kk) * 384 + c0)[lane];
            __syncthreads();

            #pragma unroll
            for (int k4 = 0; k4 < 8; k4++) {
                const float4 h0 = sh_h4[warp * 4 + 0][(k0 >> 2) + k4];
                const float4 h1 = sh_h4[warp * 4 + 1][(k0 >> 2) + k4];
                const float4 h2 = sh_h4[warp * 4 + 2][(k0 >> 2) + k4];
                const float4 h3 = sh_h4[warp * 4 + 3][(k0 >> 2) + k4];
                const float ha0[4] = {h0.x, h0.y, h0.z, h0.w};
                const float ha1[4] = {h1.x, h1.y, h1.z, h1.w};
                const float ha2[4] = {h2.x, h2.y, h2.z, h2.w};
                const float ha3[4] = {h3.x, h3.y, h3.z, h3.w};
                #pragma unroll
                for (int j = 0; j < 4; j++) {
                    const float4 wv = sh_w4[k4 * 4 + j][lane];
                    acc0.x += ha0[j] * wv.x; acc0.y += ha0[j] * wv.y; acc0.z += ha0[j] * wv.z; acc0.w += ha0[j] * wv.w;
                    acc1.x += ha1[j] * wv.x; acc1.y += ha1[j] * wv.y; acc1.z += ha1[j] * wv.z; acc1.w += ha1[j] * wv.w;
                    acc2.x += ha2[j] * wv.x; acc2.y += ha2[j] * wv.y; acc2.z += ha2[j] * wv.z; acc2.w += ha2[j] * wv.w;
                    acc3.x += ha3[j] * wv.x; acc3.y += ha3[j] * wv.y; acc3.z += ha3[j] * wv.z; acc3.w += ha3[j] * wv.w;
                }
            }
        }

        const float4 bias = reinterpret_cast<const float4*>(qkv_b + c0)[lane];
        float* dstp = (c0 == 0) ? d_q : (c0 == 128) ? d_k : d_v;
        acc0.x += bias.x; acc0.y += bias.y; acc0.z += bias.z; acc0.w += bias.w;
        acc1.x += bias.x; acc1.y += bias.y; acc1.z += bias.z; acc1.w += bias.w;
        acc2.x += bias.x; acc2.y += bias.y; acc2.z += bias.z; acc2.w += bias.w;
        acc3.x += bias.x; acc3.y += bias.y; acc3.z += bias.z; acc3.w += bias.w;
        const int rbase = row0 + warp * 4;
        if (rbase + 0 < N_NODES) reinterpret_cast<float4*>(dstp + (rbase + 0) * 128)[lane] = acc0;
        if (rbase + 1 < N_NODES) reinterpret_cast<float4*>(dstp + (rbase + 1) * 128)[lane] = acc1;
        if (rbase + 2 < N_NODES) reinterpret_cast<float4*>(dstp + (rbase + 2) * 128)[lane] = acc2;
        if (rbase + 3 < N_NODES) reinterpret_cast<float4*>(dstp + (rbase + 3) * 128)[lane] = acc3;
    }
}

// ---------------- kernel 2: per-node attention aggregate (CSR) ---------------
// One warp per destination node. q loaded once; s and e*v accumulated in
// registers; normalization fused. No atomics, no zero-init.
__global__ __launch_bounds__(256) void node_attn_kernel(
    const float* __restrict__ edge_attr)
{
    const int n = blockIdx.x * 8 + (threadIdx.x >> 5);
    if (n >= N_NODES) return;
    const int lane = threadIdx.x & 31;
    const int beg = d_rowptr[n];
    const int end = beg + d_cnt[n];

    const float4 qv = reinterpret_cast<const float4*>(d_q)[n * 32 + lane];
    float4 acc = {0.f, 0.f, 0.f, 0.f};
    float  s   = 0.f;

    for (int i = beg; i < end; i++) {
        const int2 ce  = d_csr[i];
        const int  src = ce.x;
        const int  eid = ce.y;

        float4 kv = reinterpret_cast<const float4*>(d_k)[src * 32 + lane];
        float4 av = reinterpret_cast<const float4*>(edge_attr)[eid * 32 + lane];

        float p = qv.x * (kv.x + av.x) + qv.y * (kv.y + av.y)
                + qv.z * (kv.z + av.z) + qv.w * (kv.w + av.w);
        p += __shfl_xor_sync(0xffffffffu, p, 1);
        p += __shfl_xor_sync(0xffffffffu, p, 2);   // 4 lanes/head share p

        const float ex = __expf(p * 0.25f);        // D_HEAD^-0.5
        s += ex;

        float4 vv = reinterpret_cast<const float4*>(d_v)[src * 32 + lane];
        acc.x += ex * vv.x; acc.y += ex * vv.y;
        acc.z += ex * vv.z; acc.w += ex * vv.w;
    }

    const float inv = 1.0f / fmaxf(s, 1e-16f);
    acc.x *= inv; acc.y *= inv; acc.z *= inv; acc.w *= inv;
    reinterpret_cast<float4*>(d_agg)[n * 32 + lane] = acc;
}

// ---------------- kernel 3: output projection + bias + residual --------------
__global__ __launch_bounds__(256) void out_proj_kernel(
    const float* __restrict__ x,
    const float* __restrict__ out_w,   // [128, 128] row-major
    const float* __restrict__ out_b,   // [128]
    float* __restrict__ out)
{
    __shared__ float4 sh_a4[32][32];   // 16 KB
    __shared__ float4 sh_w4[32][32];   // 16 KB

    const int tid  = threadIdx.x;
    const int warp = tid >> 5;
    const int lane = tid & 31;
    const int row0 = blockIdx.x * 32;

    for (int i = tid; i < 32 * 32; i += 256) {
        const int r   = i >> 5;
        const int g   = i & 31;
        const int row = min(row0 + r, N_NODES - 1);
        sh_a4[r][g] = reinterpret_cast<const float4*>(d_agg)[row * 32 + g];
    }

    float4 acc0 = {0,0,0,0}, acc1 = {0,0,0,0}, acc2 = {0,0,0,0}, acc3 = {0,0,0,0};

    for (int k0 = 0; k0 < 128; k0 += 32) {
        __syncthreads();
        #pragma unroll
        for (int kk = warp; kk < 32; kk += 8)
            sh_w4[kk][lane] =
                reinterpret_cast<const float4*>(out_w + (k0 + kk) * 128)[lane];
        __syncthreads();

        #pragma unroll
        for (int k4 = 0; k4 < 8; k4++) {
            const float4 a0 = sh_a4[warp * 4 + 0][(k0 >> 2) + k4];
            const float4 a1 = sh_a4[warp * 4 + 1][(k0 >> 2) + k4];
            const float4 a2 = sh_a4[warp * 4 + 2][(k0 >> 2) + k4];
            const float4 a3 = sh_a4[warp * 4 + 3][(k0 >> 2) + k4];
            const float aa0[4] = {a0.x, a0.y, a0.z, a0.w};
            const float aa1[4] = {a1.x, a1.y, a1.z, a1.w};
            const float aa2[4] = {a2.x, a2.y, a2.z, a2.w};
            const float aa3[4] = {a3.x, a3.y, a3.z, a3.w};
            #pragma unroll
            for (int j = 0; j < 4; j++) {
                const float4 wv = sh_w4[k4 * 4 + j][lane];
                acc0.x += aa0[j] * wv.x; acc0.y += aa0[j] * wv.y; acc0.z += aa0[j] * wv.z; acc0.w += aa0[j] * wv.w;
                acc1.x += aa1[j] * wv.x; acc1.y += aa1[j] * wv.y; acc1.z += aa1[j] * wv.z; acc1.w += aa1[j] * wv.w;
                acc2.x += aa2[j] * wv.x; acc2.y += aa2[j] * wv.y; acc2.z += aa2[j] * wv.z; acc2.w += aa2[j] * wv.w;
                acc3.x += aa3[j] * wv.x; acc3.y += aa3[j] * wv.y; acc3.z += aa3[j] * wv.z; acc3.w += aa3[j] * wv.w;
            }
        }
    }

    const float4 bias = reinterpret_cast<const float4*>(out_b)[lane];
    const int rbase = row0 + warp * 4;
    #pragma unroll
    for (int r = 0; r < 4; r++) {
        const int row = rbase + r;
        if (row >= N_NODES) break;
        float4 acc = (r == 0) ? acc0 : (r == 1) ? acc1 : (r == 2) ? acc2 : acc3;
        float4 xv = reinterpret_cast<const float4*>(x)[row * 32 + lane];
        float4 o;
        o.x = acc.x + bias.x + xv.x;
        o.y = acc.y + bias.y + xv.y;
        o.z = acc.z + bias.z + xv.z;
        o.w = acc.w + bias.w + xv.w;
        reinterpret_cast<float4*>(out + row * 128)[lane] = o;
    }
}

// ---------------- launcher ----------------------------------------------------
extern "C" void kernel_launch(void* const* d_in, const int* in_sizes, int n_in,
                              void* d_out, int out_size)
{
    const float* x      = (const float*)d_in[0];
    const float* ea     = (const float*)d_in[1];
    const float* qkv_w  = (const float*)d_in[2];
    const float* qkv_b  = (const float*)d_in[3];
    const float* out_w  = (const float*)d_in[4];
    const float* out_b  = (const float*)d_in[5];
    const float* ln_g   = (const float*)d_in[6];
    const float* ln_b   = (const float*)d_in[7];
    const void*  ei     = d_in[8];
    float*       out    = (float*)d_out;

    const int node_tiles = (N_NODES + 31) / 32;   // 1563

    detect_idx_kernel<<<1, 1>>>((const int*)ei);
    zero_cnt_kernel<<<(N_NODES + 255) / 256, 256>>>();
    conv_idx_kernel<<<(2 * N_EDGES + 255) / 256, 256>>>(ei);
    alloc_kernel<<<(N_NODES + 255) / 256, 256>>>();
    scatter_kernel<<<(N_EDGES + 255) / 256, 256>>>();
    ln_qkv_kernel<<<node_tiles, 256>>>(x, qkv_w, qkv_b, ln_g, ln_b);
    node_attn_kernel<<<(N_NODES + 7) / 8, 256>>>(ea);
    out_proj_kernel<<<node_tiles, 256>>>(x, out_w, out_b, out);
}